// round 7
// baseline (speedup 1.0000x reference)
#include <cuda_runtime.h>
#include <math.h>
#include <cstdint>

// B=8, A=1024, N=64, G=50, F=128
#define A_DIM 1024
#define F_DIM 128
#define G_DIM 50
#define LOG2F_CONST 0.6931471805599453f

// ---------------- device scratch ----------------
__device__ float g_xw[8 * A_DIM * F_DIM];                // x @ W_in2f  (4 MB)
__device__ float g_y [8 * A_DIM * F_DIM];                // pre-output  (4 MB)
__device__ __align__(16) float g_Wf1v[64 * F_DIM];       // W_f1 padded K=64, frag-permuted
__device__ __align__(16) float g_Wf2v[F_DIM * F_DIM];    // W_f2 frag-permuted

__device__ __forceinline__ float ssp(float x) {
    return fmaxf(x, 0.0f) + __logf(1.0f + __expf(-fabsf(x))) - LOG2F_CONST;
}
__device__ __forceinline__ float tf32r(float x) {
    uint32_t r;
    asm("cvt.rna.tf32.f32 %0, %1;" : "=r"(r) : "f"(x));
    return __uint_as_float(r);
}

// m16n8k8 row.col tf32 MMA. lane: gid=lane>>2, tig=lane&3
//   A: a0=(gid,tig) a1=(gid+8,tig) a2=(gid,tig+4) a3=(gid+8,tig+4)
//   B: b0=(k=tig,n=gid) b1=(k=tig+4,n=gid)
//   D: d0=(gid,2tig) d1=(gid,2tig+1) d2=(gid+8,2tig) d3=(gid+8,2tig+1)
__device__ __forceinline__ void mma8(float* d, const uint32_t* a, uint32_t b0, uint32_t b1) {
    asm volatile(
        "mma.sync.aligned.m16n8k8.row.col.f32.tf32.tf32.f32 "
        "{%0,%1,%2,%3}, {%4,%5,%6,%7}, {%8,%9}, {%0,%1,%2,%3};"
        : "+f"(d[0]), "+f"(d[1]), "+f"(d[2]), "+f"(d[3])
        : "r"(a[0]), "r"(a[1]), "r"(a[2]), "r"(a[3]), "r"(b0), "r"(b1));
}

// ---------------- SMEM layout (R4-proven linear tiles) ----------------
#define FS1 68            // f_ij row stride (floats), conflict-free A pattern
#define HS  132           // h row stride (floats), conflict-free A pattern
#define OFF_B1   0        // b_f1   [128]f
#define OFF_B2   512      // b_f2   [128]f
#define OFF_NBR  1024     // nbr    [128]i
#define OFF_MSK  1536     // mask   [128]f
#define OFF_FIJ  2048     // f_ij   [128][68]f = 34816 B
#define OFF_H    36864    // h / Wm [128][132]f = 67584 B
#define SMEM_TOTAL 104448

// ---------------------------------------------------------------------------
// prep: tf32-round + permute weights to fragment-vector order:
//   Wv[k][half*64 + gid*8 + ni] = W[k][half*64 + ni*8 + gid]
// so each thread's 8 B-values per k-row are contiguous (2x LDG.128).
// ---------------------------------------------------------------------------
__global__ void prep_kernel(const float* __restrict__ W_f1, const float* __restrict__ W_f2) {
    int t = threadIdx.x;
    for (int i = t; i < 64 * F_DIM; i += blockDim.x) {
        int k = i >> 7, j = i & 127;
        int half = j >> 6, gid = (j >> 3) & 7, ni = j & 7;
        int src = half * 64 + ni * 8 + gid;
        g_Wf1v[i] = (k < G_DIM) ? tf32r(W_f1[k * F_DIM + src]) : 0.0f;
    }
    for (int i = t; i < F_DIM * F_DIM; i += blockDim.x) {
        int k = i >> 7, j = i & 127;
        int half = j >> 6, gid = (j >> 3) & 7, ni = j & 7;
        int src = half * 64 + ni * 8 + gid;
        g_Wf2v[i] = tf32r(W_f2[k * F_DIM + src]);
    }
}

// ---------------------------------------------------------------------------
// dense: out[r, o] = (ssp?)(in[r,:] @ W[:,o] + bias)   — 8 rows per CTA
// ---------------------------------------------------------------------------
__global__ __launch_bounds__(F_DIM) void dense_kernel(
    const float* __restrict__ in, const float* __restrict__ W,
    const float* __restrict__ bias, float* __restrict__ outp, int apply_ssp)
{
    __shared__ float xs[8 * F_DIM];
    const int r0 = blockIdx.x * 8, o = threadIdx.x;
#pragma unroll
    for (int r = 0; r < 8; ++r)
        xs[r * F_DIM + o] = in[(size_t)(r0 + r) * F_DIM + o];
    __syncthreads();

    float a[8];
    float bb = bias ? __ldg(&bias[o]) : 0.0f;
#pragma unroll
    for (int r = 0; r < 8; ++r) a[r] = bb;
#pragma unroll 4
    for (int c = 0; c < F_DIM; ++c) {
        float w = __ldg(&W[c * F_DIM + o]);
#pragma unroll
        for (int r = 0; r < 8; ++r)
            a[r] = fmaf(xs[r * F_DIM + c], w, a[r]);
    }
#pragma unroll
    for (int r = 0; r < 8; ++r)
        outp[(size_t)(r0 + r) * F_DIM + o] = apply_ssp ? ssp(a[r]) : a[r];
}

// ---------------------------------------------------------------------------
// Main: one CTA per 2 atoms (128 neighbor rows), 256 threads, 8 warps (4M x 2N).
//   GEMM1 (mma tf32): D1[n,f] = f_ij[n,g(64)] @ Wf1[g,f]
//   epi1 : h = tf32(ssp(D1 + b1)) -> linear SMEM
//   GEMM2 (mma tf32): D2[n,k] = h[n,f] @ Wf2[f,k]
//   epi2 : Wm[n,k] = (D2 + b2[k]) * mask[n] -> SMEM (reuse h)
//   reduce: y[atom,f] = sum_n Wm[n,f] * xw[nbr[n], f]
// ---------------------------------------------------------------------------
__global__ __launch_bounds__(256) void cfconv_mma(
    const float* __restrict__ f_ij,   // [B,A,N,G]
    const float* __restrict__ mask,   // [B,A,N]
    const int*   __restrict__ nbrs,   // [B,A,N]
    const float* __restrict__ b_f1,
    const float* __restrict__ b_f2)
{
    extern __shared__ char smem[];
    float* b1s    = (float*)(smem + OFF_B1);
    float* b2s    = (float*)(smem + OFF_B2);
    int*   nbr_sh = (int*)  (smem + OFF_NBR);
    float* msk_sh = (float*)(smem + OFF_MSK);
    float* fij_s  = (float*)(smem + OFF_FIJ);
    float* h_s    = (float*)(smem + OFF_H);

    const int tid = threadIdx.x, wid = tid >> 5, lane = tid & 31;
    const int gid = lane >> 2, tig = lane & 3;
    const int c = blockIdx.x;          // atoms 2c, 2c+1
    const int b = c >> 9;              // batch

    if (tid < 128) {
        b1s[tid]    = b_f1[tid];
        b2s[tid]    = b_f2[tid];
        nbr_sh[tid] = nbrs[(size_t)c * 128 + tid];
        msk_sh[tid] = mask[(size_t)c * 128 + tid];
    }
    // stage f_ij tile [128 rows][64 cols], tf32-rounded, zero-padded
    {
        const float* fb = f_ij + (size_t)c * 128 * G_DIM;
        for (int i = tid; i < 128 * 64; i += 256) {
            int r = i >> 6, cc = i & 63;
            fij_s[r * FS1 + cc] = (cc < G_DIM) ? tf32r(__ldg(fb + r * G_DIM + cc)) : 0.0f;
        }
    }
    __syncthreads();

    const int n0 = (wid & 3) * 32;     // warp's 32 rows
    const int f0 = (wid >> 2) * 64;    // warp's 64 cols (also permuted-weight half offset)

    // ================= GEMM1: K=64 (8 k-steps) =================
    float acc[16][4];
#pragma unroll
    for (int t = 0; t < 16; ++t) { acc[t][0]=acc[t][1]=acc[t][2]=acc[t][3]=0.f; }

    {
        const uint32_t* fij_u = (const uint32_t*)fij_s;
        const float4*   wv    = (const float4*)g_Wf1v;
#pragma unroll
        for (int ks = 0; ks < 8; ++ks) {
            const int k0 = ks * 8;
            uint32_t a[2][4];
#pragma unroll
            for (int mi = 0; mi < 2; ++mi) {
                int r = (n0 + mi * 16 + gid) * FS1 + k0 + tig;
                a[mi][0] = fij_u[r];
                a[mi][1] = fij_u[r + 8 * FS1];
                a[mi][2] = fij_u[r + 4];
                a[mi][3] = fij_u[r + 8 * FS1 + 4];
            }
            // B: rows k0+tig and k0+tig+4, 8 contiguous floats each (2x LDG.128)
            int r0i = ((k0 + tig)     * F_DIM + f0 + gid * 8) >> 2;
            int r1i = ((k0 + tig + 4) * F_DIM + f0 + gid * 8) >> 2;
            float4 q0 = __ldg(wv + r0i), q1 = __ldg(wv + r0i + 1);
            float4 s0 = __ldg(wv + r1i), s1 = __ldg(wv + r1i + 1);
            uint32_t bq[8] = {__float_as_uint(q0.x),__float_as_uint(q0.y),__float_as_uint(q0.z),__float_as_uint(q0.w),
                              __float_as_uint(q1.x),__float_as_uint(q1.y),__float_as_uint(q1.z),__float_as_uint(q1.w)};
            uint32_t bs[8] = {__float_as_uint(s0.x),__float_as_uint(s0.y),__float_as_uint(s0.z),__float_as_uint(s0.w),
                              __float_as_uint(s1.x),__float_as_uint(s1.y),__float_as_uint(s1.z),__float_as_uint(s1.w)};
#pragma unroll
            for (int ni = 0; ni < 8; ++ni) {
                mma8(acc[0 * 8 + ni], a[0], bq[ni], bs[ni]);
                mma8(acc[1 * 8 + ni], a[1], bq[ni], bs[ni]);
            }
        }
    }

    // ---- epi1: h = tf32(ssp(D1 + b1)) -> linear SMEM (R4 pattern) ----
    // NOTE: weights are permuted (col = f0 + ni*8 + gid), so D columns follow
    // the same permutation: d0/d1 = cols (f0+ni*8+gid applied to n-index), i.e.
    // B col index n=gid maps to f = f0 + ni*8 + ... careful:
    // In mma, output col = B's n index = gid' of B fragment. Our B fragment for
    // step ni holds cols {f0+ni*8+gid} at lane-n position gid... Actually B
    // b0=(k=tig, n=gid) must hold W[k][col(n=gid)] -> col = f0+ni*8+gid is what
    // we loaded at vector position ni for THIS thread's gid. Each lane supplies
    // n=its own gid, so output col block ni covers f0+ni*8+0..7 exactly like R4.
    // D mapping unchanged: d0=(gid, 2tig), col index within block = 2tig.
#pragma unroll
    for (int mi = 0; mi < 2; ++mi)
#pragma unroll
        for (int ni = 0; ni < 8; ++ni) {
            float* d = acc[mi * 8 + ni];
            int f = f0 + ni * 8 + 2 * tig;
            int n = n0 + mi * 16 + gid;
            float bb0 = b1s[f], bb1 = b1s[f + 1];
            float2 v0 = make_float2(tf32r(ssp(d[0] + bb0)), tf32r(ssp(d[1] + bb1)));
            float2 v1 = make_float2(tf32r(ssp(d[2] + bb0)), tf32r(ssp(d[3] + bb1)));
            *(float2*)&h_s[n * HS + f]       = v0;
            *(float2*)&h_s[(n + 8) * HS + f] = v1;
        }
    __syncthreads();

    // ================= GEMM2: K=128 (16 k-steps) =================
#pragma unroll
    for (int t = 0; t < 16; ++t) { acc[t][0]=acc[t][1]=acc[t][2]=acc[t][3]=0.f; }

    {
        const uint32_t* h_u = (const uint32_t*)h_s;
        const float4*   wv  = (const float4*)g_Wf2v;
#pragma unroll
        for (int ks = 0; ks < 16; ++ks) {
            const int k0 = ks * 8;
            uint32_t a[2][4];
#pragma unroll
            for (int mi = 0; mi < 2; ++mi) {
                int r = (n0 + mi * 16 + gid) * HS + k0 + tig;
                a[mi][0] = h_u[r];
                a[mi][1] = h_u[r + 8 * HS];
                a[mi][2] = h_u[r + 4];
                a[mi][3] = h_u[r + 8 * HS + 4];
            }
            int r0i = ((k0 + tig)     * F_DIM + f0 + gid * 8) >> 2;
            int r1i = ((k0 + tig + 4) * F_DIM + f0 + gid * 8) >> 2;
            float4 q0 = __ldg(wv + r0i), q1 = __ldg(wv + r0i + 1);
            float4 s0 = __ldg(wv + r1i), s1 = __ldg(wv + r1i + 1);
            uint32_t bq[8] = {__float_as_uint(q0.x),__float_as_uint(q0.y),__float_as_uint(q0.z),__float_as_uint(q0.w),
                              __float_as_uint(q1.x),__float_as_uint(q1.y),__float_as_uint(q1.z),__float_as_uint(q1.w)};
            uint32_t bs[8] = {__float_as_uint(s0.x),__float_as_uint(s0.y),__float_as_uint(s0.z),__float_as_uint(s0.w),
                              __float_as_uint(s1.x),__float_as_uint(s1.y),__float_as_uint(s1.z),__float_as_uint(s1.w)};
#pragma unroll
            for (int ni = 0; ni < 8; ++ni) {
                mma8(acc[0 * 8 + ni], a[0], bq[ni], bs[ni]);
                mma8(acc[1 * 8 + ni], a[1], bq[ni], bs[ni]);
            }
        }
    }
    __syncthreads();   // all warps done reading h before overwrite

    // ---- epi2: Wm = (D2 + b2) * mask -> linear SMEM (reuse h region) ----
#pragma unroll
    for (int mi = 0; mi < 2; ++mi)
#pragma unroll
        for (int ni = 0; ni < 8; ++ni) {
            float* d = acc[mi * 8 + ni];
            int f = f0 + ni * 8 + 2 * tig;
            int n = n0 + mi * 16 + gid;
            float bb0 = b2s[f], bb1 = b2s[f + 1];
            float m0 = msk_sh[n], m1 = msk_sh[n + 8];
            *(float2*)&h_s[n * HS + f]       = make_float2((d[0] + bb0) * m0, (d[1] + bb1) * m0);
            *(float2*)&h_s[(n + 8) * HS + f] = make_float2((d[2] + bb0) * m1, (d[3] + bb1) * m1);
        }
    __syncthreads();

    // ---- reduce: y[atom, f] = sum_n Wm[n,f] * xw[nbr[n], f] ----
    {
        const int at = tid >> 7, f = tid & 127;
        const float* xwb = g_xw + (size_t)b * A_DIM * F_DIM + f;
        float y = 0.0f;
#pragma unroll 8
        for (int j = 0; j < 64; ++j) {
            int n = at * 64 + j;
            float xv = __ldg(xwb + (size_t)nbr_sh[n] * F_DIM);
            y = fmaf(h_s[n * HS + f], xv, y);
        }
        g_y[(size_t)(c * 2 + at) * F_DIM + f] = y;
    }
}

// ---------------------------------------------------------------------------
// Inputs: x, pairwise_mask, neighbors, f_ij, W_f1, b_f1, W_f2, b_f2,
//         W_in2f, W_f2out, b_f2out
// ---------------------------------------------------------------------------
extern "C" void kernel_launch(void* const* d_in, const int* in_sizes, int n_in,
                              void* d_out, int out_size)
{
    const float* x      = (const float*)d_in[0];
    const float* mask   = (const float*)d_in[1];
    const int*   nbrs   = (const int*)  d_in[2];
    const float* f_ij   = (const float*)d_in[3];
    const float* W_f1   = (const float*)d_in[4];
    const float* b_f1   = (const float*)d_in[5];
    const float* W_f2   = (const float*)d_in[6];
    const float* b_f2   = (const float*)d_in[7];
    const float* W_in2f = (const float*)d_in[8];
    const float* W_out  = (const float*)d_in[9];
    const float* b_out  = (const float*)d_in[10];
    float*       out    = (float*)d_out;

    const int BA = in_sizes[0] / F_DIM;   // 8192

    static float* xw_ptr = nullptr;
    static float* y_ptr  = nullptr;
    if (!xw_ptr) { cudaGetSymbolAddress((void**)&xw_ptr, g_xw);
                   cudaGetSymbolAddress((void**)&y_ptr,  g_y); }

    cudaFuncSetAttribute(cfconv_mma, cudaFuncAttributeMaxDynamicSharedMemorySize, SMEM_TOTAL);

    prep_kernel<<<1, 256>>>(W_f1, W_f2);
    dense_kernel<<<BA / 8, F_DIM>>>(x, W_in2f, nullptr, xw_ptr, 0);     // xw = x @ W_in2f
    cfconv_mma<<<BA / 2, 256, SMEM_TOTAL>>>(f_ij, mask, nbrs, b_f1, b_f2);
    dense_kernel<<<BA / 8, F_DIM>>>(y_ptr, W_out, b_out, out, 1);       // out = ssp(y @ W_out + b)
}

// round 8
// speedup vs baseline: 1.4630x; 1.4630x over previous
#include <cuda_runtime.h>
#include <math.h>
#include <cstdint>

// B=8, A=1024, N=64, G=50, F=128
#define A_DIM 1024
#define F_DIM 128
#define G_DIM 50
#define K1STEPS 7          // GEMM1 K = 56 >= 50 (was 64)
#define LOG2F_CONST 0.6931471805599453f

// ---------------- device scratch ----------------
__device__ float g_xw[8 * A_DIM * F_DIM];     // x @ W_in2f  (4 MB)
__device__ float g_y [8 * A_DIM * F_DIM];     // pre-output  (4 MB)
__device__ float g_Wf1p[64 * F_DIM];          // W_f1 zero-padded to K=64, tf32-rounded
__device__ float g_Wf2p[F_DIM * F_DIM];       // W_f2 tf32-rounded

__device__ __forceinline__ float ssp(float x) {
    return fmaxf(x, 0.0f) + __logf(1.0f + __expf(-fabsf(x))) - LOG2F_CONST;
}
__device__ __forceinline__ float tf32r(float x) {
    uint32_t r;
    asm("cvt.rna.tf32.f32 %0, %1;" : "=r"(r) : "f"(x));
    return __uint_as_float(r);
}

// m16n8k8 row.col tf32 MMA. lane: gid=lane>>2, tig=lane&3
//   A: a0=(gid,tig) a1=(gid+8,tig) a2=(gid,tig+4) a3=(gid+8,tig+4)
//   B: b0=(k=tig,n=gid) b1=(k=tig+4,n=gid)
//   D: d0=(gid,2tig) d1=(gid,2tig+1) d2=(gid+8,2tig) d3=(gid+8,2tig+1)
__device__ __forceinline__ void mma8(float* d, const uint32_t* a, const uint32_t* b) {
    asm volatile(
        "mma.sync.aligned.m16n8k8.row.col.f32.tf32.tf32.f32 "
        "{%0,%1,%2,%3}, {%4,%5,%6,%7}, {%8,%9}, {%0,%1,%2,%3};"
        : "+f"(d[0]), "+f"(d[1]), "+f"(d[2]), "+f"(d[3])
        : "r"(a[0]), "r"(a[1]), "r"(a[2]), "r"(a[3]), "r"(b[0]), "r"(b[1]));
}

// ---------------- SMEM layout (R4-proven linear tiles) ----------------
#define FS1 68            // f_ij row stride (floats), conflict-free A pattern
#define HS  132           // h row stride (floats), conflict-free A pattern
#define OFF_B1   0        // b_f1   [128]f
#define OFF_B2   512      // b_f2   [128]f
#define OFF_NBR  1024     // nbr    [128]i
#define OFF_MSK  1536     // mask   [128]f
#define OFF_FIJ  2048     // f_ij   [128][68]f = 34816 B
#define OFF_H    36864    // h / Wm [128][132]f = 67584 B
#define SMEM_TOTAL 104448

// ---------------------------------------------------------------------------
// prep: tf32-round + pad weights (natural [k][f] layout, as in R4)
// ---------------------------------------------------------------------------
__global__ void prep_kernel(const float* __restrict__ W_f1, const float* __restrict__ W_f2) {
    int t = threadIdx.x;
    for (int i = t; i < 64 * F_DIM; i += blockDim.x) {
        int k = i >> 7;
        g_Wf1p[i] = (k < G_DIM) ? tf32r(W_f1[i]) : 0.0f;
    }
    for (int i = t; i < F_DIM * F_DIM; i += blockDim.x)
        g_Wf2p[i] = tf32r(W_f2[i]);
}

// ---------------------------------------------------------------------------
// dense: out[r, o] = (ssp?)(in[r,:] @ W[:,o] + bias)   — 8 rows per CTA
// ---------------------------------------------------------------------------
__global__ __launch_bounds__(F_DIM) void dense_kernel(
    const float* __restrict__ in, const float* __restrict__ W,
    const float* __restrict__ bias, float* __restrict__ outp, int apply_ssp)
{
    __shared__ float xs[8 * F_DIM];
    const int r0 = blockIdx.x * 8, o = threadIdx.x;
#pragma unroll
    for (int r = 0; r < 8; ++r)
        xs[r * F_DIM + o] = in[(size_t)(r0 + r) * F_DIM + o];
    __syncthreads();

    float a[8];
    float bb = bias ? __ldg(&bias[o]) : 0.0f;
#pragma unroll
    for (int r = 0; r < 8; ++r) a[r] = bb;
#pragma unroll 4
    for (int c = 0; c < F_DIM; ++c) {
        float w = __ldg(&W[c * F_DIM + o]);
#pragma unroll
        for (int r = 0; r < 8; ++r)
            a[r] = fmaf(xs[r * F_DIM + c], w, a[r]);
    }
#pragma unroll
    for (int r = 0; r < 8; ++r)
        outp[(size_t)(r0 + r) * F_DIM + o] = apply_ssp ? ssp(a[r]) : a[r];
}

// ---------------------------------------------------------------------------
// Main: one CTA per 2 atoms (128 neighbor rows), 256 threads, 8 warps (4M x 2N).
// R4 structure, with __launch_bounds__(256,2) for guaranteed 2 CTAs/SM and
// GEMM1 trimmed to 7 k-steps (K=56 >= G=50).
// ---------------------------------------------------------------------------
__global__ __launch_bounds__(256, 2) void cfconv_mma(
    const float* __restrict__ f_ij,   // [B,A,N,G]
    const float* __restrict__ mask,   // [B,A,N]
    const int*   __restrict__ nbrs,   // [B,A,N]
    const float* __restrict__ b_f1,
    const float* __restrict__ b_f2)
{
    extern __shared__ char smem[];
    float* b1s    = (float*)(smem + OFF_B1);
    float* b2s    = (float*)(smem + OFF_B2);
    int*   nbr_sh = (int*)  (smem + OFF_NBR);
    float* msk_sh = (float*)(smem + OFF_MSK);
    float* fij_s  = (float*)(smem + OFF_FIJ);
    float* h_s    = (float*)(smem + OFF_H);

    const int tid = threadIdx.x, wid = tid >> 5, lane = tid & 31;
    const int gid = lane >> 2, tig = lane & 3;
    const int c = blockIdx.x;          // atoms 2c, 2c+1
    const int b = c >> 9;              // batch

    if (tid < 128) {
        b1s[tid]    = b_f1[tid];
        b2s[tid]    = b_f2[tid];
        nbr_sh[tid] = nbrs[(size_t)c * 128 + tid];
        msk_sh[tid] = mask[(size_t)c * 128 + tid];
    }
    // stage f_ij tile [128 rows][64 cols], tf32-rounded, zero-padded
    {
        const float* fb = f_ij + (size_t)c * 128 * G_DIM;
        for (int i = tid; i < 128 * 64; i += 256) {
            int r = i >> 6, cc = i & 63;
            fij_s[r * FS1 + cc] = (cc < G_DIM) ? tf32r(__ldg(fb + r * G_DIM + cc)) : 0.0f;
        }
    }
    __syncthreads();

    const int n0 = (wid & 3) * 32;     // warp's 32 rows
    const int f0 = (wid >> 2) * 64;    // warp's 64 cols

    // ================= GEMM1: K=56 (7 k-steps) =================
    float acc[16][4];
#pragma unroll
    for (int t = 0; t < 16; ++t) { acc[t][0]=acc[t][1]=acc[t][2]=acc[t][3]=0.f; }

    {
        const uint32_t* fij_u = (const uint32_t*)fij_s;
#pragma unroll
        for (int ks = 0; ks < K1STEPS; ++ks) {
            const int k0 = ks * 8;
            uint32_t a[2][4], bf[8][2];
#pragma unroll
            for (int mi = 0; mi < 2; ++mi) {
                int r = (n0 + mi * 16 + gid) * FS1 + k0 + tig;
                a[mi][0] = fij_u[r];
                a[mi][1] = fij_u[r + 8 * FS1];
                a[mi][2] = fij_u[r + 4];
                a[mi][3] = fij_u[r + 8 * FS1 + 4];
            }
#pragma unroll
            for (int ni = 0; ni < 8; ++ni) {
                int col = f0 + ni * 8 + gid;
                bf[ni][0] = __float_as_uint(__ldg(&g_Wf1p[(k0 + tig)     * F_DIM + col]));
                bf[ni][1] = __float_as_uint(__ldg(&g_Wf1p[(k0 + tig + 4) * F_DIM + col]));
            }
#pragma unroll
            for (int mi = 0; mi < 2; ++mi)
#pragma unroll
                for (int ni = 0; ni < 8; ++ni)
                    mma8(acc[mi * 8 + ni], a[mi], bf[ni]);
        }
    }

    // ---- epi1: h = tf32(ssp(D1 + b1)) -> linear SMEM ----
#pragma unroll
    for (int mi = 0; mi < 2; ++mi)
#pragma unroll
        for (int ni = 0; ni < 8; ++ni) {
            float* d = acc[mi * 8 + ni];
            int f = f0 + ni * 8 + 2 * tig;
            int n = n0 + mi * 16 + gid;
            float bb0 = b1s[f], bb1 = b1s[f + 1];
            float2 v0 = make_float2(tf32r(ssp(d[0] + bb0)), tf32r(ssp(d[1] + bb1)));
            float2 v1 = make_float2(tf32r(ssp(d[2] + bb0)), tf32r(ssp(d[3] + bb1)));
            *(float2*)&h_s[n * HS + f]       = v0;
            *(float2*)&h_s[(n + 8) * HS + f] = v1;
        }
    __syncthreads();

    // ================= GEMM2: K=128 (16 k-steps) =================
#pragma unroll
    for (int t = 0; t < 16; ++t) { acc[t][0]=acc[t][1]=acc[t][2]=acc[t][3]=0.f; }

    {
        const uint32_t* h_u = (const uint32_t*)h_s;
#pragma unroll
        for (int ks = 0; ks < 16; ++ks) {
            const int k0 = ks * 8;
            uint32_t a[2][4], bf[8][2];
#pragma unroll
            for (int mi = 0; mi < 2; ++mi) {
                int r = (n0 + mi * 16 + gid) * HS + k0 + tig;
                a[mi][0] = h_u[r];
                a[mi][1] = h_u[r + 8 * HS];
                a[mi][2] = h_u[r + 4];
                a[mi][3] = h_u[r + 8 * HS + 4];
            }
#pragma unroll
            for (int ni = 0; ni < 8; ++ni) {
                int col = f0 + ni * 8 + gid;
                bf[ni][0] = __float_as_uint(__ldg(&g_Wf2p[(k0 + tig)     * F_DIM + col]));
                bf[ni][1] = __float_as_uint(__ldg(&g_Wf2p[(k0 + tig + 4) * F_DIM + col]));
            }
#pragma unroll
            for (int mi = 0; mi < 2; ++mi)
#pragma unroll
                for (int ni = 0; ni < 8; ++ni)
                    mma8(acc[mi * 8 + ni], a[mi], bf[ni]);
        }
    }
    __syncthreads();   // all warps done reading h before overwrite

    // ---- epi2: Wm = (D2 + b2) * mask -> linear SMEM (reuse h region) ----
#pragma unroll
    for (int mi = 0; mi < 2; ++mi)
#pragma unroll
        for (int ni = 0; ni < 8; ++ni) {
            float* d = acc[mi * 8 + ni];
            int f = f0 + ni * 8 + 2 * tig;
            int n = n0 + mi * 16 + gid;
            float bb0 = b2s[f], bb1 = b2s[f + 1];
            float m0 = msk_sh[n], m1 = msk_sh[n + 8];
            *(float2*)&h_s[n * HS + f]       = make_float2((d[0] + bb0) * m0, (d[1] + bb1) * m0);
            *(float2*)&h_s[(n + 8) * HS + f] = make_float2((d[2] + bb0) * m1, (d[3] + bb1) * m1);
        }
    __syncthreads();

    // ---- reduce: y[atom, f] = sum_n Wm[n,f] * xw[nbr[n], f] ----
    {
        const int at = tid >> 7, f = tid & 127;
        const float* xwb = g_xw + (size_t)b * A_DIM * F_DIM + f;
        float y = 0.0f;
#pragma unroll 8
        for (int j = 0; j < 64; ++j) {
            int n = at * 64 + j;
            float xv = __ldg(xwb + (size_t)nbr_sh[n] * F_DIM);
            y = fmaf(h_s[n * HS + f], xv, y);
        }
        g_y[(size_t)(c * 2 + at) * F_DIM + f] = y;
    }
}

// ---------------------------------------------------------------------------
// Inputs: x, pairwise_mask, neighbors, f_ij, W_f1, b_f1, W_f2, b_f2,
//         W_in2f, W_f2out, b_f2out
// ---------------------------------------------------------------------------
extern "C" void kernel_launch(void* const* d_in, const int* in_sizes, int n_in,
                              void* d_out, int out_size)
{
    const float* x      = (const float*)d_in[0];
    const float* mask   = (const float*)d_in[1];
    const int*   nbrs   = (const int*)  d_in[2];
    const float* f_ij   = (const float*)d_in[3];
    const float* W_f1   = (const float*)d_in[4];
    const float* b_f1   = (const float*)d_in[5];
    const float* W_f2   = (const float*)d_in[6];
    const float* b_f2   = (const float*)d_in[7];
    const float* W_in2f = (const float*)d_in[8];
    const float* W_out  = (const float*)d_in[9];
    const float* b_out  = (const float*)d_in[10];
    float*       out    = (float*)d_out;

    const int BA = in_sizes[0] / F_DIM;   // 8192

    static float* xw_ptr = nullptr;
    static float* y_ptr  = nullptr;
    if (!xw_ptr) { cudaGetSymbolAddress((void**)&xw_ptr, g_xw);
                   cudaGetSymbolAddress((void**)&y_ptr,  g_y); }

    cudaFuncSetAttribute(cfconv_mma, cudaFuncAttributeMaxDynamicSharedMemorySize, SMEM_TOTAL);

    prep_kernel<<<1, 256>>>(W_f1, W_f2);
    dense_kernel<<<BA / 8, F_DIM>>>(x, W_in2f, nullptr, xw_ptr, 0);     // xw = x @ W_in2f
    cfconv_mma<<<BA / 2, 256, SMEM_TOTAL>>>(f_ij, mask, nbrs, b_f1, b_f2);
    dense_kernel<<<BA / 8, F_DIM>>>(y_ptr, W_out, b_out, out, 1);       // out = ssp(y @ W_out + b)
}